// round 15
// baseline (speedup 1.0000x reference)
#include <cuda_runtime.h>
#include <math.h>

#define BB   8
#define LL   2000
#define EE   300
#define EEP  320      // e padded to k32 multiple
#define EEP2 (EEP/2)  // 160 bf16x2 pairs
#define NLB  8922
#define LWW  10
#define FF   200
#define KK   10
#define HH   200
#define FEAT 500
#define LP   1991     // L - K + 1
#define LPAD 2048     // padded Lp
#define CKK  3000     // conv GEMM K = E*K

// ---------------- scratch (static device allocations; no cudaMalloc) ----------
__device__ float    g_avg[NLB * EE];                        // 10.7 MB
__device__ unsigned g_avgb[NLB * EEP2];                     // 5.7 MB bf16x2 [n][e/2]
__device__ float    g_gemb[NLB * FEAT];                     // 17.8 MB
__device__ float    g_c[(size_t)BB * LP * FF];              // 12.7 MB [B][Lp][F]
__device__ unsigned g_pjTb[(size_t)BB * EEP2 * LPAD];       // 10.5 MB bf16x2 [b][e/2][l]
__device__ unsigned g_scores_u[(size_t)BB * NLB * (LPAD / 2)];  // 292 MB bf16x2
__device__ unsigned g_cbu[(size_t)BB * (LPAD / 2) * 256];   // 8.4 MB bf16x2 [b][l/2][n]
__device__ float    g_ao[(size_t)BB * NLB * FF];            // 57 MB
__device__ float    g_xeT[(size_t)BB * EE * LL];            // 19.2 MB [B][E][L]
__device__ float    g_wcT[CKK * FF];                        // 2.4 MB  [(e,k)][F]
__device__ float    g_losspart[64];

// ---------------- mma helpers --------------------------------------------------
__device__ __forceinline__ unsigned cvt_tf32(float x) {
    unsigned u;
    asm("cvt.rna.tf32.f32 %0, %1;" : "=r"(u) : "f"(x));
    return u;
}

__device__ __forceinline__ void mma_tf32(float* d, const unsigned* a, const unsigned* b) {
    asm volatile(
        "mma.sync.aligned.m16n8k8.row.col.f32.tf32.tf32.f32 "
        "{%0,%1,%2,%3}, {%4,%5,%6,%7}, {%8,%9}, {%0,%1,%2,%3};"
        : "+f"(d[0]), "+f"(d[1]), "+f"(d[2]), "+f"(d[3])
        : "r"(a[0]), "r"(a[1]), "r"(a[2]), "r"(a[3]), "r"(b[0]), "r"(b[1]));
}

__device__ __forceinline__ void mma_bf16(float* d, const unsigned* a, const unsigned* b) {
    asm volatile(
        "mma.sync.aligned.m16n8k16.row.col.f32.bf16.bf16.f32 "
        "{%0,%1,%2,%3}, {%4,%5,%6,%7}, {%8,%9}, {%0,%1,%2,%3};"
        : "+f"(d[0]), "+f"(d[1]), "+f"(d[2]), "+f"(d[3])
        : "r"(a[0]), "r"(a[1]), "r"(a[2]), "r"(a[3]), "r"(b[0]), "r"(b[1]));
}

// pack two floats into bf16x2 (lo = first arg in low 16 bits)
__device__ __forceinline__ unsigned pack_bf16x2(float lo, float hi) {
    unsigned u;
    asm("cvt.rn.bf16x2.f32 %0, %1, %2;" : "=r"(u) : "f"(hi), "f"(lo));
    return u;
}

__device__ __forceinline__ float fexp(float x) {
    float r;
    asm("ex2.approx.f32 %0, %1;" : "=f"(r) : "f"(x * 1.4426950408889634f));
    return r;
}

// ---------------- 1. average label embedding (+ bf16 copy) --------------------
__global__ void k_avg(const float* __restrict__ we, const int* __restrict__ lidx,
                      const float* __restrict__ lmask) {
    int n = blockIdx.x;
    int t = threadIdx.x;
    __shared__ int   idx_s[LWW];
    __shared__ float m_s[LWW];
    __shared__ float inv;
    __shared__ float sv[EEP];
    if (t < LWW) { idx_s[t] = lidx[n * LWW + t]; m_s[t] = lmask[n * LWW + t]; }
    if (t < EEP) sv[t] = 0.f;
    __syncthreads();
    if (t == 0) {
        float s = 0.f;
        for (int w = 0; w < LWW; w++) s += m_s[w];
        inv = 1.f / s;
    }
    __syncthreads();
    if (t < EE) {
        float s = 0.f;
        for (int w = 0; w < LWW; w++)
            s += we[(size_t)idx_s[w] * EE + t] * m_s[w];
        float v = s * inv;
        g_avg[(size_t)n * EE + t] = v;
        sv[t] = v;
    }
    __syncthreads();
    if (t < EEP2)
        g_avgb[n * EEP2 + t] = pack_bf16x2(sv[2 * t], sv[2 * t + 1]);
}

// ---------------- 2. sparse graph aggregate + Wg + concat ---------------------
__global__ void k_graph(const float* __restrict__ adj, const float* __restrict__ nn,
                        const float* __restrict__ Wg, const float* __restrict__ bg) {
    int n = blockIdx.x;
    int t = threadIdx.x;
    __shared__ int   list[256];
    __shared__ int   cnt;
    __shared__ float agg_s[EE];
    if (t == 0) cnt = 0;
    __syncthreads();
    for (int j = t; j < NLB; j += blockDim.x) {
        if (adj[(size_t)n * NLB + j] != 0.f) {
            int p = atomicAdd(&cnt, 1);
            if (p < 256) list[p] = j;
        }
    }
    __syncthreads();
    int m = cnt < 256 ? cnt : 256;
    if (t == 0) {            // deterministic ascending order
        for (int i = 1; i < m; i++) {
            int v = list[i], j = i - 1;
            while (j >= 0 && list[j] > v) { list[j + 1] = list[j]; j--; }
            list[j + 1] = v;
        }
    }
    __syncthreads();
    float invd = 1.f / nn[n];
    if (t < EE) {
        float s = 0.f;
        for (int i = 0; i < m; i++) s += g_avg[(size_t)list[i] * EE + t];
        agg_s[t] = s * invd;
        g_gemb[(size_t)n * FEAT + t] = g_avg[(size_t)n * EE + t];
    }
    __syncthreads();
    if (t < HH) {
        float s = bg[t];
        for (int e = 0; e < EE; e++) s += agg_s[e] * Wg[e * HH + t];
        g_gemb[(size_t)n * FEAT + EE + t] = fmaxf(s, 0.f);
    }
}

// ---------------- 3a. xeT[b][e][l] = we[x[b][l]][e] * mask[b][l] --------------
__global__ void k_embT(const int* __restrict__ x, const float* __restrict__ mask,
                       const float* __restrict__ we) {
    __shared__ int   xi[128];
    __shared__ float mk[128];
    int b  = blockIdx.y;
    int l0 = blockIdx.x * 128;
    int t  = threadIdx.x;
    if (t < 128) {
        int gl = l0 + t;
        xi[t] = (gl < LL) ? x[b * LL + gl] : 0;
        mk[t] = (gl < LL) ? mask[b * LL + gl] : 0.f;
    }
    __syncthreads();
    int l = t & 127, e0 = t >> 7;
    int gl = l0 + l;
    if (gl < LL) {
        const float* wr = we + (size_t)xi[l] * EE;
        float m = mk[l];
        for (int e = e0; e < EE; e += 2)
            g_xeT[((size_t)b * EE + e) * LL + gl] = wr[e] * m;
    }
}

// ---------------- 3b. WcT[(e*K+k)][f] = Wc[f][e][k] ---------------------------
__global__ void k_wct(const float* __restrict__ Wc) {
    int idx = blockIdx.x * 256 + threadIdx.x;
    if (idx < CKK * FF) {
        int c = idx / FF, f = idx % FF;
        g_wcT[idx] = Wc[(size_t)f * CKK + c];
    }
}

// ---------------- 3c. conv GEMM (tf32): c = relu(im2col(xeT) @ WcT + bc) ------
__global__ void __launch_bounds__(256) k_convg(const float* __restrict__ bc) {
    __shared__ __align__(16) unsigned sA[2][2][8][32][4];
    __shared__ __align__(16) unsigned sB[2][2][16][32][2];

    int b  = blockIdx.z;
    int m0 = blockIdx.x * 128;      // l
    int n0 = blockIdx.y * 128;      // f
    const float* Ap = g_xeT + (size_t)b * EE * LL;

    int t = threadIdx.x, lane = t & 31, wid = t >> 5;
    int wm = wid >> 1, wn = wid & 1;

    float acc[2][8][4];
    #pragma unroll
    for (int i = 0; i < 2; i++)
        #pragma unroll
        for (int j = 0; j < 8; j++)
            #pragma unroll
            for (int q = 0; q < 4; q++) acc[i][j][q] = 0.f;

    float ra[2][4];
    float rb[4][2];

    auto loadA = [&](int k0) {
        #pragma unroll
        for (int s = 0; s < 2; s++) {
            int slot = t + s * 256;
            int ls = slot & 31, tm = (slot >> 5) & 7, k8 = slot >> 8;
            int r  = m0 + tm * 16 + (ls >> 2);
            int c  = k0 + k8 * 8 + (ls & 3);
            int c2 = c + 4;
            int e1 = c / KK,  o1 = c  - e1 * KK;
            int e2 = c2 / KK, o2 = c2 - e2 * KK;
            bool rv0 = r < LP, rv1 = (r + 8) < LP;
            bool cv1 = c < CKK, cv2 = c2 < CKK;
            ra[s][0] = (rv0 && cv1) ? Ap[(size_t)e1 * LL + r + o1]     : 0.f;
            ra[s][1] = (rv1 && cv1) ? Ap[(size_t)e1 * LL + r + 8 + o1] : 0.f;
            ra[s][2] = (rv0 && cv2) ? Ap[(size_t)e2 * LL + r + o2]     : 0.f;
            ra[s][3] = (rv1 && cv2) ? Ap[(size_t)e2 * LL + r + 8 + o2] : 0.f;
        }
    };
    auto loadB = [&](int k0) {
        #pragma unroll
        for (int s = 0; s < 4; s++) {
            int slot = t + s * 256;
            int ls = slot & 31, tn = (slot >> 5) & 15, k8 = slot >> 9;
            int k = k0 + k8 * 8 + (ls & 3);
            int n = n0 + tn * 8 + (ls >> 2);
            bool nv = n < FF;
            rb[s][0] = (k < CKK && nv)       ? g_wcT[(size_t)k * FF + n]       : 0.f;
            rb[s][1] = ((k + 4) < CKK && nv) ? g_wcT[(size_t)(k + 4) * FF + n] : 0.f;
        }
    };
    auto storeS = [&](int buf) {
        #pragma unroll
        for (int s = 0; s < 2; s++) {
            int slot = t + s * 256;
            int ls = slot & 31, tm = (slot >> 5) & 7, k8 = slot >> 8;
            unsigned* d = &sA[buf][k8][tm][ls][0];
            d[0] = cvt_tf32(ra[s][0]); d[1] = cvt_tf32(ra[s][1]);
            d[2] = cvt_tf32(ra[s][2]); d[3] = cvt_tf32(ra[s][3]);
        }
        #pragma unroll
        for (int s = 0; s < 4; s++) {
            int slot = t + s * 256;
            int ls = slot & 31, tn = (slot >> 5) & 15, k8 = slot >> 9;
            unsigned* d = &sB[buf][k8][tn][ls][0];
            d[0] = cvt_tf32(rb[s][0]); d[1] = cvt_tf32(rb[s][1]);
        }
    };
    auto compute = [&](int buf) {
        #pragma unroll
        for (int k8 = 0; k8 < 2; k8++) {
            unsigned af[2][4], bf[8][2];
            #pragma unroll
            for (int i = 0; i < 2; i++)
                *(uint4*)af[i] = *(const uint4*)&sA[buf][k8][wm * 2 + i][lane][0];
            #pragma unroll
            for (int j = 0; j < 8; j++)
                *(uint2*)bf[j] = *(const uint2*)&sB[buf][k8][wn * 8 + j][lane][0];
            #pragma unroll
            for (int i = 0; i < 2; i++)
                #pragma unroll
                for (int j = 0; j < 8; j++)
                    mma_tf32(acc[i][j], af[i], bf[j]);
        }
    };

    const int S = (CKK + 15) / 16;   // 188
    loadA(0); loadB(0); storeS(0);
    __syncthreads();
    for (int s = 0; s < S; s++) {
        if (s + 1 < S) { loadA((s + 1) * 16); loadB((s + 1) * 16); }
        compute(s & 1);
        if (s + 1 < S) storeS((s + 1) & 1);
        __syncthreads();
    }

    #pragma unroll
    for (int i = 0; i < 2; i++) {
        int row = m0 + (wm * 2 + i) * 16 + (lane >> 2);
        #pragma unroll
        for (int j = 0; j < 8; j++) {
            int col = n0 + (wn * 8 + j) * 8 + (lane & 3) * 2;
            if (col < FF) {
                float b0 = bc[col], b1 = bc[col + 1];
                if (row < LP) {
                    float2 o = make_float2(fmaxf(acc[i][j][0] + b0, 0.f),
                                           fmaxf(acc[i][j][1] + b1, 0.f));
                    *(float2*)&g_c[((size_t)b * LP + row) * FF + col] = o;
                }
                if (row + 8 < LP) {
                    float2 o = make_float2(fmaxf(acc[i][j][2] + b0, 0.f),
                                           fmaxf(acc[i][j][3] + b1, 0.f));
                    *(float2*)&g_c[((size_t)b * LP + row + 8) * FF + col] = o;
                }
            }
        }
    }
}

// ---------------- 3d. pack c -> bf16x2 [b][l/2][256] (col 200 = ones) ---------
__global__ void k_cprep() {
    int idx = blockIdx.x * 256 + threadIdx.x;   // b*(1024*256) + k2*256 + n
    int n  = idx & 255;
    int k2 = (idx >> 8) & (LPAD / 2 - 1);
    int b  = idx >> 18;
    int l  = 2 * k2;
    float v0 = 0.f, v1 = 0.f;
    if (n < FF) {
        const float* cb = g_c + (size_t)b * LP * FF + n;
        if (l < LP)     v0 = cb[(size_t)l * FF];
        if (l + 1 < LP) v1 = cb[(size_t)(l + 1) * FF];
    } else if (n == FF) {
        if (l < LP)     v0 = 1.f;
        if (l + 1 < LP) v1 = 1.f;
    }
    g_cbu[idx] = pack_bf16x2(v0, v1);
}

// ---------------- 4. pj GEMM (tf32): pjTb = bf16(tanh(c @ Wp + bp))^T ---------
__global__ void __launch_bounds__(256) k_pjg(const float* __restrict__ Wp,
                                             const float* __restrict__ bp) {
    __shared__ __align__(16) unsigned sA[2][2][8][32][4];
    __shared__ __align__(16) unsigned sB[2][2][16][32][2];

    int b  = blockIdx.z;
    int m0 = blockIdx.x * 128;      // l
    int n0 = blockIdx.y * 128;      // e
    const float* Ap = g_c + (size_t)b * LP * FF;

    int t = threadIdx.x, lane = t & 31, wid = t >> 5;
    int wm = wid >> 1, wn = wid & 1;

    float acc[2][8][4];
    #pragma unroll
    for (int i = 0; i < 2; i++)
        #pragma unroll
        for (int j = 0; j < 8; j++)
            #pragma unroll
            for (int q = 0; q < 4; q++) acc[i][j][q] = 0.f;

    float ra[2][4];
    float rb[4][2];

    auto loadA = [&](int k0) {
        #pragma unroll
        for (int s = 0; s < 2; s++) {
            int slot = t + s * 256;
            int ls = slot & 31, tm = (slot >> 5) & 7, k8 = slot >> 8;
            int r = m0 + tm * 16 + (ls >> 2);
            int c = k0 + k8 * 8 + (ls & 3);
            bool rv0 = r < LP, rv1 = (r + 8) < LP;
            bool cv0 = c < FF, cv1 = (c + 4) < FF;
            ra[s][0] = (rv0 && cv0) ? Ap[(size_t)r * FF + c]           : 0.f;
            ra[s][1] = (rv1 && cv0) ? Ap[(size_t)(r + 8) * FF + c]     : 0.f;
            ra[s][2] = (rv0 && cv1) ? Ap[(size_t)r * FF + c + 4]       : 0.f;
            ra[s][3] = (rv1 && cv1) ? Ap[(size_t)(r + 8) * FF + c + 4] : 0.f;
        }
    };
    auto loadB = [&](int k0) {
        #pragma unroll
        for (int s = 0; s < 4; s++) {
            int slot = t + s * 256;
            int ls = slot & 31, tn = (slot >> 5) & 15, k8 = slot >> 9;
            int k = k0 + k8 * 8 + (ls & 3);
            int n = n0 + tn * 8 + (ls >> 2);
            bool nv = n < EE;
            rb[s][0] = (k < FF && nv)       ? Wp[(size_t)k * EE + n]       : 0.f;
            rb[s][1] = ((k + 4) < FF && nv) ? Wp[(size_t)(k + 4) * EE + n] : 0.f;
        }
    };
    auto storeS = [&](int buf) {
        #pragma unroll
        for (int s = 0; s < 2; s++) {
            int slot = t + s * 256;
            int ls = slot & 31, tm = (slot >> 5) & 7, k8 = slot >> 8;
            unsigned* d = &sA[buf][k8][tm][ls][0];
            d[0] = cvt_tf32(ra[s][0]); d[1] = cvt_tf32(ra[s][1]);
            d[2] = cvt_tf32(ra[s][2]); d[3] = cvt_tf32(ra[s][3]);
        }
        #pragma unroll
        for (int s = 0; s < 4; s++) {
            int slot = t + s * 256;
            int ls = slot & 31, tn = (slot >> 5) & 15, k8 = slot >> 9;
            unsigned* d = &sB[buf][k8][tn][ls][0];
            d[0] = cvt_tf32(rb[s][0]); d[1] = cvt_tf32(rb[s][1]);
        }
    };
    auto compute = [&](int buf) {
        #pragma unroll
        for (int k8 = 0; k8 < 2; k8++) {
            unsigned af[2][4], bf[8][2];
            #pragma unroll
            for (int i = 0; i < 2; i++)
                *(uint4*)af[i] = *(const uint4*)&sA[buf][k8][wm * 2 + i][lane][0];
            #pragma unroll
            for (int j = 0; j < 8; j++)
                *(uint2*)bf[j] = *(const uint2*)&sB[buf][k8][wn * 8 + j][lane][0];
            #pragma unroll
            for (int i = 0; i < 2; i++)
                #pragma unroll
                for (int j = 0; j < 8; j++)
                    mma_tf32(acc[i][j], af[i], bf[j]);
        }
    };

    const int S = (FF + 15) / 16;    // 13
    loadA(0); loadB(0); storeS(0);
    __syncthreads();
    for (int s = 0; s < S; s++) {
        if (s + 1 < S) { loadA((s + 1) * 16); loadB((s + 1) * 16); }
        compute(s & 1);
        if (s + 1 < S) storeS((s + 1) & 1);
        __syncthreads();
    }

    // epilogue: tanh -> bf16x2 pairs along e, [b][e/2][l]; pads stay zero-init
    unsigned* pjb = g_pjTb + (size_t)b * EEP2 * LPAD;
    #pragma unroll
    for (int i = 0; i < 2; i++) {
        int row = m0 + (wm * 2 + i) * 16 + (lane >> 2);
        #pragma unroll
        for (int j = 0; j < 8; j++) {
            int col = n0 + (wn * 8 + j) * 8 + (lane & 3) * 2;
            if (col < EE) {
                float b0 = bp[col], b1 = bp[col + 1];
                if (row < LP)
                    pjb[(size_t)(col >> 1) * LPAD + row] =
                        pack_bf16x2(tanhf(acc[i][j][0] + b0), tanhf(acc[i][j][1] + b1));
                if (row + 8 < LP)
                    pjb[(size_t)(col >> 1) * LPAD + row + 8] =
                        pack_bf16x2(tanhf(acc[i][j][2] + b0), tanhf(acc[i][j][3] + b1));
            }
        }
    }
}

// ---------------- 5a. scores GEMM (bf16, K32 stages): exp(avg @ pjT) ----------
__global__ void __launch_bounds__(256) k_scores() {
    __shared__ __align__(16) unsigned sA[2][2][8][32][4];   // [buf][kh][tm][lane][p]
    __shared__ __align__(16) unsigned sB[2][2][16][32][2];  // [buf][kh][tn][lane][p]

    int b  = blockIdx.z;
    int m0 = blockIdx.x * 128;
    int n0 = blockIdx.y * 128;
    const unsigned* Bp = g_pjTb + (size_t)b * EEP2 * LPAD;

    int t = threadIdx.x, lane = t & 31, wid = t >> 5;
    int wm = wid >> 1, wn = wid & 1;

    float acc[2][8][4];
    #pragma unroll
    for (int i = 0; i < 2; i++)
        #pragma unroll
        for (int j = 0; j < 8; j++)
            #pragma unroll
            for (int q = 0; q < 4; q++) acc[i][j][q] = 0.f;

    unsigned raA[8], raB[8];

    auto loadA = [&](int k0) {
        #pragma unroll
        for (int s = 0; s < 8; s++) {
            int slot = t + s * 256;
            int ls = slot & 31, tm = (slot >> 5) & 7, p = (slot >> 8) & 3, kh = slot >> 10;
            int r = m0 + tm * 16 + (ls >> 2) + (p & 1) * 8;
            int c = k0 + kh * 16 + (ls & 3) * 2 + (p >> 1) * 8;
            raA[s] = (r < NLB) ? g_avgb[r * EEP2 + (c >> 1)] : 0u;
        }
    };
    auto loadB = [&](int k0) {
        #pragma unroll
        for (int s = 0; s < 8; s++) {
            int slot = t + s * 256;
            int ls = slot & 31, tn = (slot >> 5) & 15, p = (slot >> 9) & 1, kh = slot >> 10;
            int k = k0 + kh * 16 + (ls & 3) * 2 + p * 8;
            int l = n0 + tn * 8 + (ls >> 2);
            raB[s] = Bp[(size_t)(k >> 1) * LPAD + l];
        }
    };
    auto storeS = [&](int buf) {
        #pragma unroll
        for (int s = 0; s < 8; s++) {
            int slot = t + s * 256;
            int ls = slot & 31, tm = (slot >> 5) & 7, p = (slot >> 8) & 3, kh = slot >> 10;
            sA[buf][kh][tm][ls][p] = raA[s];
        }
        #pragma unroll
        for (int s = 0; s < 8; s++) {
            int slot = t + s * 256;
            int ls = slot & 31, tn = (slot >> 5) & 15, p = (slot >> 9) & 1, kh = slot >> 10;
            sB[buf][kh][tn][ls][p] = raB[s];
        }
    };
    auto compute = [&](int buf) {
        #pragma unroll
        for (int kh = 0; kh < 2; kh++) {
            unsigned af[2][4], bf[8][2];
            #pragma unroll
            for (int i = 0; i < 2; i++)
                *(uint4*)af[i] = *(const uint4*)&sA[buf][kh][wm * 2 + i][lane][0];
            #pragma unroll
            for (int j = 0; j < 8; j++)
                *(uint2*)bf[j] = *(const uint2*)&sB[buf][kh][wn * 8 + j][lane][0];
            #pragma unroll
            for (int i = 0; i < 2; i++)
                #pragma unroll
                for (int j = 0; j < 8; j++)
                    mma_bf16(acc[i][j], af[i], bf[j]);
        }
    };

    const int S = EEP / 32;   // 10 stages
    loadA(0); loadB(0); storeS(0);
    __syncthreads();
    for (int s = 0; s < S; s++) {
        if (s + 1 < S) { loadA((s + 1) * 32); loadB((s + 1) * 32); }
        compute(s & 1);
        if (s + 1 < S) storeS((s + 1) & 1);
        __syncthreads();
    }

    // epilogue: fast exp (no max-sub; |scores| << 1), pad cols -> 0, bf16x2 out
    unsigned* So = g_scores_u + (size_t)b * NLB * (LPAD / 2);
    #pragma unroll
    for (int i = 0; i < 2; i++) {
        int row = m0 + (wm * 2 + i) * 16 + (lane >> 2);
        #pragma unroll
        for (int j = 0; j < 8; j++) {
            int col = n0 + (wn * 8 + j) * 8 + (lane & 3) * 2;
            float e0 = (col < LP)     ? fexp(acc[i][j][0]) : 0.f;
            float e1 = (col + 1 < LP) ? fexp(acc[i][j][1]) : 0.f;
            float e2 = (col < LP)     ? fexp(acc[i][j][2]) : 0.f;
            float e3 = (col + 1 < LP) ? fexp(acc[i][j][3]) : 0.f;
            if (row < NLB)
                So[(size_t)row * (LPAD / 2) + (col >> 1)] = pack_bf16x2(e0, e1);
            if (row + 8 < NLB)
                So[(size_t)(row + 8) * (LPAD / 2) + (col >> 1)] = pack_bf16x2(e2, e3);
        }
    }
}

// ---------------- 5b. attn_out GEMM (bf16, K32, 512 thr, ones-col rowsum) -----
__global__ void __launch_bounds__(512, 1) k_attnout() {
    __shared__ __align__(16) unsigned sA[2][2][8][32][4];   // 16 KB
    __shared__ __align__(16) unsigned sB[2][2][32][32][2];  // 32 KB
    __shared__ float rowred[128];

    int b  = blockIdx.x;
    int m0 = blockIdx.y * 128;
    const unsigned* Ap = g_scores_u + (size_t)b * NLB * (LPAD / 2);
    const unsigned* Bp = g_cbu + (size_t)b * (LPAD / 2) * 256;

    int t = threadIdx.x, lane = t & 31, wid = t >> 5;
    int wm = wid >> 2, wn = wid & 3;

    float acc[2][8][4];
    #pragma unroll
    for (int i = 0; i < 2; i++)
        #pragma unroll
        for (int j = 0; j < 8; j++)
            #pragma unroll
            for (int q = 0; q < 4; q++) acc[i][j][q] = 0.f;

    unsigned raA[4], raB[8];

    auto loadA = [&](int k0) {
        #pragma unroll
        for (int s = 0; s < 4; s++) {
            int slot = t + s * 512;
            int ls = slot & 31, tm = (slot >> 5) & 7, p = (slot >> 8) & 3, kh = slot >> 10;
            int r = m0 + tm * 16 + (ls >> 2) + (p & 1) * 8;
            int c = k0 + kh * 16 + (ls & 3) * 2 + (p >> 1) * 8;
            raA[s] = (r < NLB) ? Ap[(size_t)r * (LPAD / 2) + (c >> 1)] : 0u;
        }
    };
    auto loadB = [&](int k0) {
        #pragma unroll
        for (int s = 0; s < 8; s++) {
            int slot = t + s * 512;
            int ls = slot & 31, tn = (slot >> 5) & 31, p = (slot >> 10) & 1, kh = slot >> 11;
            int k = k0 + kh * 16 + (ls & 3) * 2 + p * 8;
            int n = tn * 8 + (ls >> 2);
            raB[s] = Bp[(size_t)(k >> 1) * 256 + n];
        }
    };
    auto storeS = [&](int buf) {
        #pragma unroll
        for (int s = 0; s < 4; s++) {
            int slot = t + s * 512;
            int ls = slot & 31, tm = (slot >> 5) & 7, p = (slot >> 8) & 3, kh = slot >> 10;
            sA[buf][kh][tm][ls][p] = raA[s];
        }
        #pragma unroll
        for (int s = 0; s < 8; s++) {
            int slot = t + s * 512;
            int ls = slot & 31, tn = (slot >> 5) & 31, p = (slot >> 10) & 1, kh = slot >> 11;
            sB[buf][kh][tn][ls][p] = raB[s];
        }
    };
    auto compute = [&](int buf) {
        #pragma unroll
        for (int kh = 0; kh < 2; kh++) {
            unsigned af[2][4], bf[8][2];
            #pragma unroll
            for (int i = 0; i < 2; i++)
                *(uint4*)af[i] = *(const uint4*)&sA[buf][kh][wm * 2 + i][lane][0];
            #pragma unroll
            for (int j = 0; j < 8; j++)
                *(uint2*)bf[j] = *(const uint2*)&sB[buf][kh][wn * 8 + j][lane][0];
            #pragma unroll
            for (int i = 0; i < 2; i++)
                #pragma unroll
                for (int j = 0; j < 8; j++)
                    mma_bf16(acc[i][j], af[i], bf[j]);
        }
    };

    const int S = LPAD / 32;   // 64 stages
    loadA(0); loadB(0); storeS(0);
    __syncthreads();
    for (int s = 0; s < S; s++) {
        if (s + 1 < S) { loadA((s + 1) * 32); loadB((s + 1) * 32); }
        compute(s & 1);
        if (s + 1 < S) storeS((s + 1) & 1);
        __syncthreads();
    }

    // rowsum lives at col 200: wn==3, j==1, (lane&3)==0, element 0 of each half
    if (wn == 3 && (lane & 3) == 0) {
        #pragma unroll
        for (int i = 0; i < 2; i++)
            #pragma unroll
            for (int h = 0; h < 2; h++)
                rowred[wm * 32 + i * 16 + (lane >> 2) + h * 8] = acc[i][1][h * 2];
    }
    __syncthreads();

    #pragma unroll
    for (int i = 0; i < 2; i++)
        #pragma unroll
        for (int h = 0; h < 2; h++) {
            int rloc = wm * 32 + i * 16 + (lane >> 2) + h * 8;
            int grow = m0 + rloc;
            if (grow < NLB) {
                float inv = 1.f / rowred[rloc];
                #pragma unroll
                for (int j = 0; j < 8; j++) {
                    int f = wn * 64 + j * 8 + (lane & 3) * 2;
                    if (f < FF) {
                        float2 o = make_float2(acc[i][j][h * 2 + 0] * inv,
                                               acc[i][j][h * 2 + 1] * inv);
                        *(float2*)&g_ao[((size_t)(b * NLB + grow)) * FF + f] = o;
                    }
                }
            }
        }
}

// ---------------- 5d. proj GEMM (tf32) fused with gemb dot -> logits ----------
__global__ void __launch_bounds__(256) k_projg(const float* __restrict__ Wo,
                                               const float* __restrict__ bo,
                                               float* __restrict__ out) {
    __shared__ __align__(16) unsigned sA[2][2][8][32][4];
    __shared__ __align__(16) unsigned sB[2][2][16][32][2];
    __shared__ float sred[256];

    int b  = blockIdx.y;
    int m0 = blockIdx.x * 128;
    const float* Ap = g_ao + (size_t)b * NLB * FF;

    int t = threadIdx.x, lane = t & 31, wid = t >> 5;
    int wm = wid >> 1, wn = wid & 1;

    float part[2][2] = {{0.f, 0.f}, {0.f, 0.f}};   // [i][row / row+8]
    float ra[2][4];
    float rb[4][2];
    float acc[2][8][4];

    auto loadA = [&](int k0) {
        #pragma unroll
        for (int s = 0; s < 2; s++) {
            int slot = t + s * 256;
            int ls = slot & 31, tm = (slot >> 5) & 7, k8 = slot >> 8;
            int r = m0 + tm * 16 + (ls >> 2);
            int c = k0 + k8 * 8 + (ls & 3);
            bool rv0 = r < NLB, rv1 = (r + 8) < NLB;
            bool cv0 = c < FF, cv1 = (c + 4) < FF;
            ra[s][0] = (rv0 && cv0) ? Ap[(size_t)r * FF + c]           : 0.f;
            ra[s][1] = (rv1 && cv0) ? Ap[(size_t)(r + 8) * FF + c]     : 0.f;
            ra[s][2] = (rv0 && cv1) ? Ap[(size_t)r * FF + c + 4]       : 0.f;
            ra[s][3] = (rv1 && cv1) ? Ap[(size_t)(r + 8) * FF + c + 4] : 0.f;
        }
    };
    auto loadB = [&](int k0, int n0) {
        #pragma unroll
        for (int s = 0; s < 4; s++) {
            int slot = t + s * 256;
            int ls = slot & 31, tn = (slot >> 5) & 15, k8 = slot >> 9;
            int k = k0 + k8 * 8 + (ls & 3);
            int n = n0 + tn * 8 + (ls >> 2);
            bool nv = n < FEAT;
            rb[s][0] = (k < FF && nv)       ? Wo[(size_t)k * FEAT + n]       : 0.f;
            rb[s][1] = ((k + 4) < FF && nv) ? Wo[(size_t)(k + 4) * FEAT + n] : 0.f;
        }
    };
    auto storeS = [&](int buf) {
        #pragma unroll
        for (int s = 0; s < 2; s++) {
            int slot = t + s * 256;
            int ls = slot & 31, tm = (slot >> 5) & 7, k8 = slot >> 8;
            unsigned* d = &sA[buf][k8][tm][ls][0];
            d[0] = cvt_tf32(ra[s][0]); d[1] = cvt_tf32(ra[s][1]);
            d[2] = cvt_tf32(ra[s][2]); d[3] = cvt_tf32(ra[s][3]);
        }
        #pragma unroll
        for (int s = 0; s < 4; s++) {
            int slot = t + s * 256;
            int ls = slot & 31, tn = (slot >> 5) & 15, k8 = slot >> 9;
            unsigned* d = &sB[buf][k8][tn][ls][0];
            d[0] = cvt_tf32(rb[s][0]); d[1] = cvt_tf32(rb[s][1]);
        }
    };
    auto compute = [&](int buf) {
        #pragma unroll
        for (int k8 = 0; k8 < 2; k8++) {
            unsigned af[2][4], bf[8][2];
            #pragma unroll
            for (int i = 0; i < 2; i++)
                *(uint4*)af[i] = *(const uint4*)&sA[buf][k8][wm * 2 + i][lane][0];
            #pragma unroll
            for (int j = 0; j < 8; j++)
                *(uint2*)bf[j] = *(const uint2*)&sB[buf][k8][wn * 8 + j][lane][0];
            #pragma unroll
            for (int i = 0; i < 2; i++)
                #pragma unroll
                for (int j = 0; j < 8; j++)
                    mma_tf32(acc[i][j], af[i], bf[j]);
        }
    };

    const int S = (FF + 15) / 16;    // 13
    for (int nt = 0; nt < 4; nt++) {
        int n0 = nt * 128;
        #pragma unroll
        for (int i = 0; i < 2; i++)
            #pragma unroll
            for (int j = 0; j < 8; j++)
                #pragma unroll
                for (int q = 0; q < 4; q++) acc[i][j][q] = 0.f;

        loadA(0); loadB(0, n0); storeS(0);
        __syncthreads();
        for (int s = 0; s < S; s++) {
            if (s + 1 < S) { loadA((s + 1) * 16); loadB((s + 1) * 16, n0); }
            compute(s & 1);
            if (s + 1 < S) storeS((s + 1) & 1);
            __syncthreads();
        }

        // fold: relu(acc + bo) * gemb into per-row partials
        #pragma unroll
        for (int i = 0; i < 2; i++) {
            int row = m0 + (wm * 2 + i) * 16 + (lane >> 2);
            const float* g0 = (row < NLB)     ? g_gemb + (size_t)row * FEAT       : g_gemb;
            const float* g1 = (row + 8 < NLB) ? g_gemb + (size_t)(row + 8) * FEAT : g_gemb;
            bool rv0 = row < NLB, rv1 = (row + 8) < NLB;
            #pragma unroll
            for (int j = 0; j < 8; j++) {
                int col = n0 + (wn * 8 + j) * 8 + (lane & 3) * 2;
                if (col < FEAT) {
                    float b0 = bo[col], b1 = bo[col + 1];
                    if (rv0)
                        part[i][0] += fmaxf(acc[i][j][0] + b0, 0.f) * g0[col]
                                    + fmaxf(acc[i][j][1] + b1, 0.f) * g0[col + 1];
                    if (rv1)
                        part[i][1] += fmaxf(acc[i][j][2] + b0, 0.f) * g1[col]
                                    + fmaxf(acc[i][j][3] + b1, 0.f) * g1[col + 1];
                }
            }
        }
        __syncthreads();
    }

    // reduce across quad lanes (cols), then across the 2 wn warps via smem
    #pragma unroll
    for (int i = 0; i < 2; i++) {
        #pragma unroll
        for (int h = 0; h < 2; h++) {
            float v = part[i][h];
            v += __shfl_xor_sync(~0u, v, 1);
            v += __shfl_xor_sync(~0u, v, 2);
            if ((lane & 3) == 0) {
                int rl = wm * 32 + i * 16 + (lane >> 2) + h * 8;
                sred[rl * 2 + wn] = v;
            }
        }
    }
    __syncthreads();
    if (t < 128) {
        int gn = m0 + t;
        if (gn < NLB)
            out[b * NLB + gn] = sred[t * 2] + sred[t * 2 + 1];
    }
}

// ---------------- 6. BCE loss (deterministic two-stage) -----------------------
__global__ void k_loss_part(const float* __restrict__ y, const float* __restrict__ logits) {
    __shared__ float red[256];
    float s = 0.f;
    for (int i = blockIdx.x * 256 + threadIdx.x; i < BB * NLB; i += 64 * 256) {
        float z = logits[i];
        float yy = y[i];
        s += fmaxf(z, 0.f) - z * yy + log1pf(expf(-fabsf(z)));
    }
    red[threadIdx.x] = s;
    __syncthreads();
    for (int o = 128; o; o >>= 1) {
        if (threadIdx.x < o) red[threadIdx.x] += red[threadIdx.x + o];
        __syncthreads();
    }
    if (threadIdx.x == 0) g_losspart[blockIdx.x] = red[0];
}

__global__ void k_loss_final(float* __restrict__ out) {
    if (threadIdx.x == 0) {
        float s = 0.f;
        for (int i = 0; i < 64; i++) s += g_losspart[i];
        out[BB * NLB] = s / (float)BB;
    }
}

// ---------------- launch -------------------------------------------------------
extern "C" void kernel_launch(void* const* d_in, const int* in_sizes, int n_in,
                              void* d_out, int out_size) {
    const int*   x     = (const int*)d_in[0];
    const float* y     = (const float*)d_in[1];
    const float* mask  = (const float*)d_in[2];
    const float* we    = (const float*)d_in[3];
    const int*   lidx  = (const int*)d_in[4];
    const float* lmask = (const float*)d_in[5];
    const float* adj   = (const float*)d_in[6];
    const float* nn    = (const float*)d_in[7];
    const float* Wg    = (const float*)d_in[8];
    const float* bg    = (const float*)d_in[9];
    const float* Wc    = (const float*)d_in[10];
    const float* bc    = (const float*)d_in[11];
    const float* Wp    = (const float*)d_in[12];
    const float* bp    = (const float*)d_in[13];
    const float* Wo    = (const float*)d_in[14];
    const float* bo    = (const float*)d_in[15];
    float* out = (float*)d_out;

    k_avg<<<NLB, 320>>>(we, lidx, lmask);
    k_graph<<<NLB, 320>>>(adj, nn, Wg, bg);

    dim3 ge((LL + 127) / 128, BB);
    k_embT<<<ge, 256>>>(x, mask, we);
    k_wct<<<(CKK * FF + 255) / 256, 256>>>(Wc);

    dim3 gv((LP + 127) / 128, 2, BB);        // 16 x 2 x 8
    k_convg<<<gv, 256>>>(bc);

    k_cprep<<<(BB * (LPAD / 2) * 256) / 256, 256>>>();

    dim3 gj((LP + 127) / 128, 3, BB);        // 16 x 3 x 8
    k_pjg<<<gj, 256>>>(Wp, bp);

    dim3 gs((NLB + 127) / 128, LPAD / 128, BB);      // 70 x 16 x 8
    k_scores<<<gs, 256>>>();

    dim3 go(BB, (NLB + 127) / 128);          // 8 x 70
    k_attnout<<<go, 512>>>();

    dim3 gp((NLB + 127) / 128, BB);          // 70 x 8
    k_projg<<<gp, 256>>>(Wo, bo, out);

    k_loss_part<<<64, 256>>>(y, out);
    k_loss_final<<<1, 32>>>(out);
}

// round 17
// speedup vs baseline: 1.3820x; 1.3820x over previous
#include <cuda_runtime.h>
#include <math.h>

#define BB   8
#define LL   2000
#define EE   300
#define EEP  304      // e padded to k16 multiple
#define EEP2 (EEP/2)  // 152 bf16x2 pairs
#define NLB  8922
#define LWW  10
#define FF   200
#define KK   10
#define HH   200
#define FEAT 500
#define LP   1991     // L - K + 1
#define LPAD 2048     // padded Lp
#define CKK  3000     // conv GEMM K = E*K

// ---------------- scratch (static device allocations; no cudaMalloc) ----------
__device__ float    g_avg[NLB * EE];                        // 10.7 MB
__device__ unsigned g_avgb[NLB * EEP2];                     // 5.4 MB bf16x2 [n][e/2]
__device__ float    g_gemb[NLB * FEAT];                     // 17.8 MB
__device__ float    g_c[(size_t)BB * LP * FF];              // 12.7 MB [B][Lp][F]
__device__ unsigned g_pjTb[(size_t)BB * EEP2 * LPAD];       // 10.0 MB bf16x2 [b][e/2][l]
__device__ unsigned g_scores_u[(size_t)BB * NLB * (LPAD / 2)];  // 292 MB bf16x2
__device__ unsigned g_cbu[(size_t)BB * (LPAD / 2) * 256];   // 8.4 MB bf16x2 [b][l/2][n]
__device__ float    g_ao[(size_t)BB * NLB * FF];            // 57 MB
__device__ float    g_xeT[(size_t)BB * EE * LL];            // 19.2 MB [B][E][L]
__device__ float    g_wcT[CKK * FF];                        // 2.4 MB  [(e,k)][F]
__device__ float    g_losspart[64];

// ---------------- mma helpers --------------------------------------------------
__device__ __forceinline__ unsigned cvt_tf32(float x) {
    unsigned u;
    asm("cvt.rna.tf32.f32 %0, %1;" : "=r"(u) : "f"(x));
    return u;
}

__device__ __forceinline__ void mma_tf32(float* d, const unsigned* a, const unsigned* b) {
    asm volatile(
        "mma.sync.aligned.m16n8k8.row.col.f32.tf32.tf32.f32 "
        "{%0,%1,%2,%3}, {%4,%5,%6,%7}, {%8,%9}, {%0,%1,%2,%3};"
        : "+f"(d[0]), "+f"(d[1]), "+f"(d[2]), "+f"(d[3])
        : "r"(a[0]), "r"(a[1]), "r"(a[2]), "r"(a[3]), "r"(b[0]), "r"(b[1]));
}

__device__ __forceinline__ void mma_bf16(float* d, const unsigned* a, const unsigned* b) {
    asm volatile(
        "mma.sync.aligned.m16n8k16.row.col.f32.bf16.bf16.f32 "
        "{%0,%1,%2,%3}, {%4,%5,%6,%7}, {%8,%9}, {%0,%1,%2,%3};"
        : "+f"(d[0]), "+f"(d[1]), "+f"(d[2]), "+f"(d[3])
        : "r"(a[0]), "r"(a[1]), "r"(a[2]), "r"(a[3]), "r"(b[0]), "r"(b[1]));
}

// pack two floats into bf16x2 (lo = first arg in low 16 bits)
__device__ __forceinline__ unsigned pack_bf16x2(float lo, float hi) {
    unsigned u;
    asm("cvt.rn.bf16x2.f32 %0, %1, %2;" : "=r"(u) : "f"(hi), "f"(lo));
    return u;
}

__device__ __forceinline__ float fexp(float x) {
    float r;
    asm("ex2.approx.f32 %0, %1;" : "=f"(r) : "f"(x * 1.4426950408889634f));
    return r;
}

// ---------------- 1. average label embedding (+ bf16 copy) --------------------
__global__ void k_avg(const float* __restrict__ we, const int* __restrict__ lidx,
                      const float* __restrict__ lmask) {
    int n = blockIdx.x;
    int t = threadIdx.x;
    __shared__ int   idx_s[LWW];
    __shared__ float m_s[LWW];
    __shared__ float inv;
    __shared__ float sv[EEP];
    if (t < LWW) { idx_s[t] = lidx[n * LWW + t]; m_s[t] = lmask[n * LWW + t]; }
    if (t < EEP) sv[t] = 0.f;
    __syncthreads();
    if (t == 0) {
        float s = 0.f;
        for (int w = 0; w < LWW; w++) s += m_s[w];
        inv = 1.f / s;
    }
    __syncthreads();
    if (t < EE) {
        float s = 0.f;
        for (int w = 0; w < LWW; w++)
            s += we[(size_t)idx_s[w] * EE + t] * m_s[w];
        float v = s * inv;
        g_avg[(size_t)n * EE + t] = v;
        sv[t] = v;
    }
    __syncthreads();
    if (t < EEP2)
        g_avgb[n * EEP2 + t] = pack_bf16x2(sv[2 * t], sv[2 * t + 1]);
}

// ---------------- 2. sparse graph aggregate + Wg + concat ---------------------
__global__ void k_graph(const float* __restrict__ adj, const float* __restrict__ nn,
                        const float* __restrict__ Wg, const float* __restrict__ bg) {
    int n = blockIdx.x;
    int t = threadIdx.x;
    __shared__ int   list[256];
    __shared__ int   cnt;
    __shared__ float agg_s[EE];
    if (t == 0) cnt = 0;
    __syncthreads();
    for (int j = t; j < NLB; j += blockDim.x) {
        if (adj[(size_t)n * NLB + j] != 0.f) {
            int p = atomicAdd(&cnt, 1);
            if (p < 256) list[p] = j;
        }
    }
    __syncthreads();
    int m = cnt < 256 ? cnt : 256;
    if (t == 0) {            // deterministic ascending order
        for (int i = 1; i < m; i++) {
            int v = list[i], j = i - 1;
            while (j >= 0 && list[j] > v) { list[j + 1] = list[j]; j--; }
            list[j + 1] = v;
        }
    }
    __syncthreads();
    float invd = 1.f / nn[n];
    if (t < EE) {
        float s = 0.f;
        for (int i = 0; i < m; i++) s += g_avg[(size_t)list[i] * EE + t];
        agg_s[t] = s * invd;
        g_gemb[(size_t)n * FEAT + t] = g_avg[(size_t)n * EE + t];
    }
    __syncthreads();
    if (t < HH) {
        float s = bg[t];
        for (int e = 0; e < EE; e++) s += agg_s[e] * Wg[e * HH + t];
        g_gemb[(size_t)n * FEAT + EE + t] = fmaxf(s, 0.f);
    }
}

// ---------------- 3a. xeT[b][e][l] = we[x[b][l]][e] * mask[b][l] --------------
__global__ void k_embT(const int* __restrict__ x, const float* __restrict__ mask,
                       const float* __restrict__ we) {
    __shared__ int   xi[128];
    __shared__ float mk[128];
    int b  = blockIdx.y;
    int l0 = blockIdx.x * 128;
    int t  = threadIdx.x;
    if (t < 128) {
        int gl = l0 + t;
        xi[t] = (gl < LL) ? x[b * LL + gl] : 0;
        mk[t] = (gl < LL) ? mask[b * LL + gl] : 0.f;
    }
    __syncthreads();
    int l = t & 127, e0 = t >> 7;
    int gl = l0 + l;
    if (gl < LL) {
        const float* wr = we + (size_t)xi[l] * EE;
        float m = mk[l];
        for (int e = e0; e < EE; e += 2)
            g_xeT[((size_t)b * EE + e) * LL + gl] = wr[e] * m;
    }
}

// ---------------- 3b. WcT[(e*K+k)][f] = Wc[f][e][k] ---------------------------
__global__ void k_wct(const float* __restrict__ Wc) {
    int idx = blockIdx.x * 256 + threadIdx.x;
    if (idx < CKK * FF) {
        int c = idx / FF, f = idx % FF;
        g_wcT[idx] = Wc[(size_t)f * CKK + c];
    }
}

// ---------------- 3c. conv GEMM (tf32): c = relu(im2col(xeT) @ WcT + bc) ------
__global__ void __launch_bounds__(256) k_convg(const float* __restrict__ bc) {
    __shared__ __align__(16) unsigned sA[2][2][8][32][4];
    __shared__ __align__(16) unsigned sB[2][2][16][32][2];

    int b  = blockIdx.z;
    int m0 = blockIdx.x * 128;      // l
    int n0 = blockIdx.y * 128;      // f
    const float* Ap = g_xeT + (size_t)b * EE * LL;

    int t = threadIdx.x, lane = t & 31, wid = t >> 5;
    int wm = wid >> 1, wn = wid & 1;

    float acc[2][8][4];
    #pragma unroll
    for (int i = 0; i < 2; i++)
        #pragma unroll
        for (int j = 0; j < 8; j++)
            #pragma unroll
            for (int q = 0; q < 4; q++) acc[i][j][q] = 0.f;

    float ra[2][4];
    float rb[4][2];

    auto loadA = [&](int k0) {
        #pragma unroll
        for (int s = 0; s < 2; s++) {
            int slot = t + s * 256;
            int ls = slot & 31, tm = (slot >> 5) & 7, k8 = slot >> 8;
            int r  = m0 + tm * 16 + (ls >> 2);
            int c  = k0 + k8 * 8 + (ls & 3);
            int c2 = c + 4;
            int e1 = c / KK,  o1 = c  - e1 * KK;
            int e2 = c2 / KK, o2 = c2 - e2 * KK;
            bool rv0 = r < LP, rv1 = (r + 8) < LP;
            bool cv1 = c < CKK, cv2 = c2 < CKK;
            ra[s][0] = (rv0 && cv1) ? Ap[(size_t)e1 * LL + r + o1]     : 0.f;
            ra[s][1] = (rv1 && cv1) ? Ap[(size_t)e1 * LL + r + 8 + o1] : 0.f;
            ra[s][2] = (rv0 && cv2) ? Ap[(size_t)e2 * LL + r + o2]     : 0.f;
            ra[s][3] = (rv1 && cv2) ? Ap[(size_t)e2 * LL + r + 8 + o2] : 0.f;
        }
    };
    auto loadB = [&](int k0) {
        #pragma unroll
        for (int s = 0; s < 4; s++) {
            int slot = t + s * 256;
            int ls = slot & 31, tn = (slot >> 5) & 15, k8 = slot >> 9;
            int k = k0 + k8 * 8 + (ls & 3);
            int n = n0 + tn * 8 + (ls >> 2);
            bool nv = n < FF;
            rb[s][0] = (k < CKK && nv)       ? g_wcT[(size_t)k * FF + n]       : 0.f;
            rb[s][1] = ((k + 4) < CKK && nv) ? g_wcT[(size_t)(k + 4) * FF + n] : 0.f;
        }
    };
    auto storeS = [&](int buf) {
        #pragma unroll
        for (int s = 0; s < 2; s++) {
            int slot = t + s * 256;
            int ls = slot & 31, tm = (slot >> 5) & 7, k8 = slot >> 8;
            unsigned* d = &sA[buf][k8][tm][ls][0];
            d[0] = cvt_tf32(ra[s][0]); d[1] = cvt_tf32(ra[s][1]);
            d[2] = cvt_tf32(ra[s][2]); d[3] = cvt_tf32(ra[s][3]);
        }
        #pragma unroll
        for (int s = 0; s < 4; s++) {
            int slot = t + s * 256;
            int ls = slot & 31, tn = (slot >> 5) & 15, k8 = slot >> 9;
            unsigned* d = &sB[buf][k8][tn][ls][0];
            d[0] = cvt_tf32(rb[s][0]); d[1] = cvt_tf32(rb[s][1]);
        }
    };
    auto compute = [&](int buf) {
        #pragma unroll
        for (int k8 = 0; k8 < 2; k8++) {
            unsigned af[2][4], bf[8][2];
            #pragma unroll
            for (int i = 0; i < 2; i++)
                *(uint4*)af[i] = *(const uint4*)&sA[buf][k8][wm * 2 + i][lane][0];
            #pragma unroll
            for (int j = 0; j < 8; j++)
                *(uint2*)bf[j] = *(const uint2*)&sB[buf][k8][wn * 8 + j][lane][0];
            #pragma unroll
            for (int i = 0; i < 2; i++)
                #pragma unroll
                for (int j = 0; j < 8; j++)
                    mma_tf32(acc[i][j], af[i], bf[j]);
        }
    };

    const int S = (CKK + 15) / 16;   // 188
    loadA(0); loadB(0); storeS(0);
    __syncthreads();
    for (int s = 0; s < S; s++) {
        if (s + 1 < S) { loadA((s + 1) * 16); loadB((s + 1) * 16); }
        compute(s & 1);
        if (s + 1 < S) storeS((s + 1) & 1);
        __syncthreads();
    }

    #pragma unroll
    for (int i = 0; i < 2; i++) {
        int row = m0 + (wm * 2 + i) * 16 + (lane >> 2);
        #pragma unroll
        for (int j = 0; j < 8; j++) {
            int col = n0 + (wn * 8 + j) * 8 + (lane & 3) * 2;
            if (col < FF) {
                float b0 = bc[col], b1 = bc[col + 1];
                if (row < LP) {
                    float2 o = make_float2(fmaxf(acc[i][j][0] + b0, 0.f),
                                           fmaxf(acc[i][j][1] + b1, 0.f));
                    *(float2*)&g_c[((size_t)b * LP + row) * FF + col] = o;
                }
                if (row + 8 < LP) {
                    float2 o = make_float2(fmaxf(acc[i][j][2] + b0, 0.f),
                                           fmaxf(acc[i][j][3] + b1, 0.f));
                    *(float2*)&g_c[((size_t)b * LP + row + 8) * FF + col] = o;
                }
            }
        }
    }
}

// ---------------- 3d. pack c -> bf16x2 [b][l/2][256] (col 200 = ones) ---------
__global__ void k_cprep() {
    int idx = blockIdx.x * 256 + threadIdx.x;   // b*(1024*256) + k2*256 + n
    int n  = idx & 255;
    int k2 = (idx >> 8) & (LPAD / 2 - 1);
    int b  = idx >> 18;
    int l  = 2 * k2;
    float v0 = 0.f, v1 = 0.f;
    if (n < FF) {
        const float* cb = g_c + (size_t)b * LP * FF + n;
        if (l < LP)     v0 = cb[(size_t)l * FF];
        if (l + 1 < LP) v1 = cb[(size_t)(l + 1) * FF];
    } else if (n == FF) {
        if (l < LP)     v0 = 1.f;
        if (l + 1 < LP) v1 = 1.f;
    }
    g_cbu[idx] = pack_bf16x2(v0, v1);
}

// ---------------- 4. pj GEMM (tf32): pjTb = bf16(tanh(c @ Wp + bp))^T ---------
__global__ void __launch_bounds__(256) k_pjg(const float* __restrict__ Wp,
                                             const float* __restrict__ bp) {
    __shared__ __align__(16) unsigned sA[2][2][8][32][4];
    __shared__ __align__(16) unsigned sB[2][2][16][32][2];

    int b  = blockIdx.z;
    int m0 = blockIdx.x * 128;      // l
    int n0 = blockIdx.y * 128;      // e
    const float* Ap = g_c + (size_t)b * LP * FF;

    int t = threadIdx.x, lane = t & 31, wid = t >> 5;
    int wm = wid >> 1, wn = wid & 1;

    float acc[2][8][4];
    #pragma unroll
    for (int i = 0; i < 2; i++)
        #pragma unroll
        for (int j = 0; j < 8; j++)
            #pragma unroll
            for (int q = 0; q < 4; q++) acc[i][j][q] = 0.f;

    float ra[2][4];
    float rb[4][2];

    auto loadA = [&](int k0) {
        #pragma unroll
        for (int s = 0; s < 2; s++) {
            int slot = t + s * 256;
            int ls = slot & 31, tm = (slot >> 5) & 7, k8 = slot >> 8;
            int r = m0 + tm * 16 + (ls >> 2);
            int c = k0 + k8 * 8 + (ls & 3);
            bool rv0 = r < LP, rv1 = (r + 8) < LP;
            bool cv0 = c < FF, cv1 = (c + 4) < FF;
            ra[s][0] = (rv0 && cv0) ? Ap[(size_t)r * FF + c]           : 0.f;
            ra[s][1] = (rv1 && cv0) ? Ap[(size_t)(r + 8) * FF + c]     : 0.f;
            ra[s][2] = (rv0 && cv1) ? Ap[(size_t)r * FF + c + 4]       : 0.f;
            ra[s][3] = (rv1 && cv1) ? Ap[(size_t)(r + 8) * FF + c + 4] : 0.f;
        }
    };
    auto loadB = [&](int k0) {
        #pragma unroll
        for (int s = 0; s < 4; s++) {
            int slot = t + s * 256;
            int ls = slot & 31, tn = (slot >> 5) & 15, k8 = slot >> 9;
            int k = k0 + k8 * 8 + (ls & 3);
            int n = n0 + tn * 8 + (ls >> 2);
            bool nv = n < EE;
            rb[s][0] = (k < FF && nv)       ? Wp[(size_t)k * EE + n]       : 0.f;
            rb[s][1] = ((k + 4) < FF && nv) ? Wp[(size_t)(k + 4) * EE + n] : 0.f;
        }
    };
    auto storeS = [&](int buf) {
        #pragma unroll
        for (int s = 0; s < 2; s++) {
            int slot = t + s * 256;
            int ls = slot & 31, tm = (slot >> 5) & 7, k8 = slot >> 8;
            unsigned* d = &sA[buf][k8][tm][ls][0];
            d[0] = cvt_tf32(ra[s][0]); d[1] = cvt_tf32(ra[s][1]);
            d[2] = cvt_tf32(ra[s][2]); d[3] = cvt_tf32(ra[s][3]);
        }
        #pragma unroll
        for (int s = 0; s < 4; s++) {
            int slot = t + s * 256;
            int ls = slot & 31, tn = (slot >> 5) & 15, k8 = slot >> 9;
            unsigned* d = &sB[buf][k8][tn][ls][0];
            d[0] = cvt_tf32(rb[s][0]); d[1] = cvt_tf32(rb[s][1]);
        }
    };
    auto compute = [&](int buf) {
        #pragma unroll
        for (int k8 = 0; k8 < 2; k8++) {
            unsigned af[2][4], bf[8][2];
            #pragma unroll
            for (int i = 0; i < 2; i++)
                *(uint4*)af[i] = *(const uint4*)&sA[buf][k8][wm * 2 + i][lane][0];
            #pragma unroll
            for (int j = 0; j < 8; j++)
                *(uint2*)bf[j] = *(const uint2*)&sB[buf][k8][wn * 8 + j][lane][0];
            #pragma unroll
            for (int i = 0; i < 2; i++)
                #pragma unroll
                for (int j = 0; j < 8; j++)
                    mma_tf32(acc[i][j], af[i], bf[j]);
        }
    };

    const int S = (FF + 15) / 16;    // 13
    loadA(0); loadB(0); storeS(0);
    __syncthreads();
    for (int s = 0; s < S; s++) {
        if (s + 1 < S) { loadA((s + 1) * 16); loadB((s + 1) * 16); }
        compute(s & 1);
        if (s + 1 < S) storeS((s + 1) & 1);
        __syncthreads();
    }

    // epilogue: tanh -> bf16x2 pairs along e, [b][e/2][l]; pads stay zero-init
    unsigned* pjb = g_pjTb + (size_t)b * EEP2 * LPAD;
    #pragma unroll
    for (int i = 0; i < 2; i++) {
        int row = m0 + (wm * 2 + i) * 16 + (lane >> 2);
        #pragma unroll
        for (int j = 0; j < 8; j++) {
            int col = n0 + (wn * 8 + j) * 8 + (lane & 3) * 2;
            if (col < EE) {
                float b0 = bp[col], b1 = bp[col + 1];
                if (row < LP)
                    pjb[(size_t)(col >> 1) * LPAD + row] =
                        pack_bf16x2(tanhf(acc[i][j][0] + b0), tanhf(acc[i][j][1] + b1));
                if (row + 8 < LP)
                    pjb[(size_t)(col >> 1) * LPAD + row + 8] =
                        pack_bf16x2(tanhf(acc[i][j][2] + b0), tanhf(acc[i][j][3] + b1));
            }
        }
    }
}

// ---------------- 5a. scores GEMM (bf16): exp(avg @ pjT) -> bf16 --------------
__global__ void __launch_bounds__(256) k_scores() {
    __shared__ __align__(16) unsigned sA[2][8][32][4];   // [buf][tm][lane][p]
    __shared__ __align__(16) unsigned sB[2][16][32][2];  // [buf][tn][lane][p]

    int b  = blockIdx.z;
    int m0 = blockIdx.x * 128;
    int n0 = blockIdx.y * 128;
    const unsigned* Bp = g_pjTb + (size_t)b * EEP2 * LPAD;

    int t = threadIdx.x, lane = t & 31, wid = t >> 5;
    int wm = wid >> 1, wn = wid & 1;

    float acc[2][8][4];
    #pragma unroll
    for (int i = 0; i < 2; i++)
        #pragma unroll
        for (int j = 0; j < 8; j++)
            #pragma unroll
            for (int q = 0; q < 4; q++) acc[i][j][q] = 0.f;

    unsigned raA[4], raB[4];

    auto loadA = [&](int k0) {
        #pragma unroll
        for (int s = 0; s < 4; s++) {
            int slot = t + s * 256;
            int ls = slot & 31, tm = (slot >> 5) & 7, p = slot >> 8;
            int r = m0 + tm * 16 + (ls >> 2) + (p & 1) * 8;
            int c = k0 + (ls & 3) * 2 + (p >> 1) * 8;
            raA[s] = (r < NLB) ? g_avgb[r * EEP2 + (c >> 1)] : 0u;
        }
    };
    auto loadB = [&](int k0) {
        #pragma unroll
        for (int s = 0; s < 4; s++) {
            int slot = t + s * 256;
            int ls = slot & 31, tn = (slot >> 5) & 15, p = slot >> 9;
            int k = k0 + (ls & 3) * 2 + p * 8;
            int l = n0 + tn * 8 + (ls >> 2);
            raB[s] = Bp[(size_t)(k >> 1) * LPAD + l];
        }
    };
    auto storeS = [&](int buf) {
        #pragma unroll
        for (int s = 0; s < 4; s++) {
            int slot = t + s * 256;
            int ls = slot & 31, tm = (slot >> 5) & 7, p = slot >> 8;
            sA[buf][tm][ls][p] = raA[s];
        }
        #pragma unroll
        for (int s = 0; s < 4; s++) {
            int slot = t + s * 256;
            int ls = slot & 31, tn = (slot >> 5) & 15, p = slot >> 9;
            sB[buf][tn][ls][p] = raB[s];
        }
    };
    auto compute = [&](int buf) {
        unsigned af[2][4], bf[8][2];
        #pragma unroll
        for (int i = 0; i < 2; i++)
            *(uint4*)af[i] = *(const uint4*)&sA[buf][wm * 2 + i][lane][0];
        #pragma unroll
        for (int j = 0; j < 8; j++)
            *(uint2*)bf[j] = *(const uint2*)&sB[buf][wn * 8 + j][lane][0];
        #pragma unroll
        for (int i = 0; i < 2; i++)
            #pragma unroll
            for (int j = 0; j < 8; j++)
                mma_bf16(acc[i][j], af[i], bf[j]);
    };

    const int S = EEP / 16;   // 19 stages
    loadA(0); loadB(0); storeS(0);
    __syncthreads();
    for (int s = 0; s < S; s++) {
        if (s + 1 < S) { loadA((s + 1) * 16); loadB((s + 1) * 16); }
        compute(s & 1);
        if (s + 1 < S) storeS((s + 1) & 1);
        __syncthreads();
    }

    // epilogue: fast exp (no max-sub; |scores| << 1), pad cols -> 0, bf16x2 out
    unsigned* So = g_scores_u + (size_t)b * NLB * (LPAD / 2);
    #pragma unroll
    for (int i = 0; i < 2; i++) {
        int row = m0 + (wm * 2 + i) * 16 + (lane >> 2);
        #pragma unroll
        for (int j = 0; j < 8; j++) {
            int col = n0 + (wn * 8 + j) * 8 + (lane & 3) * 2;
            float e0 = (col < LP)     ? fexp(acc[i][j][0]) : 0.f;
            float e1 = (col + 1 < LP) ? fexp(acc[i][j][1]) : 0.f;
            float e2 = (col < LP)     ? fexp(acc[i][j][2]) : 0.f;
            float e3 = (col + 1 < LP) ? fexp(acc[i][j][3]) : 0.f;
            if (row < NLB)
                So[(size_t)row * (LPAD / 2) + (col >> 1)] = pack_bf16x2(e0, e1);
            if (row + 8 < NLB)
                So[(size_t)(row + 8) * (LPAD / 2) + (col >> 1)] = pack_bf16x2(e2, e3);
        }
    }
}

// ---------------- 5b. attn_out GEMM (bf16, M64 tile, 256 thr, 2 CTA/SM) -------
// block tile 64(labels) x 256(F=200 data + col 200 = ones -> rowsum).
// 8 warps = 2m x 4n; warp tile 32 x 64. Epilogue: O / O[:,200] -> g_ao.
__global__ void __launch_bounds__(256, 2) k_attnout() {
    __shared__ __align__(16) unsigned sA[2][4][32][4];   // 4 KB
    __shared__ __align__(16) unsigned sB[2][32][32][2];  // 16 KB
    __shared__ float rowred[64];

    int b  = blockIdx.x;
    int m0 = blockIdx.y * 64;
    const unsigned* Ap = g_scores_u + (size_t)b * NLB * (LPAD / 2);
    const unsigned* Bp = g_cbu + (size_t)b * (LPAD / 2) * 256;

    int t = threadIdx.x, lane = t & 31, wid = t >> 5;
    int wm = wid >> 2, wn = wid & 3;

    float acc[2][8][4];
    #pragma unroll
    for (int i = 0; i < 2; i++)
        #pragma unroll
        for (int j = 0; j < 8; j++)
            #pragma unroll
            for (int q = 0; q < 4; q++) acc[i][j][q] = 0.f;

    unsigned raA[2], raB[8];

    auto loadA = [&](int k0) {
        #pragma unroll
        for (int s = 0; s < 2; s++) {
            int slot = t + s * 256;
            int ls = slot & 31, tm = (slot >> 5) & 3, p = slot >> 7;
            int r = m0 + tm * 16 + (ls >> 2) + (p & 1) * 8;
            int c = k0 + (ls & 3) * 2 + (p >> 1) * 8;
            raA[s] = (r < NLB) ? Ap[(size_t)r * (LPAD / 2) + (c >> 1)] : 0u;
        }
    };
    auto loadB = [&](int k0) {
        #pragma unroll
        for (int s = 0; s < 8; s++) {
            int slot = t + s * 256;
            int ls = slot & 31, tn = (slot >> 5) & 31, p = slot >> 10;
            int k = k0 + (ls & 3) * 2 + p * 8;
            int n = tn * 8 + (ls >> 2);
            raB[s] = Bp[(size_t)(k >> 1) * 256 + n];
        }
    };
    auto storeS = [&](int buf) {
        #pragma unroll
        for (int s = 0; s < 2; s++) {
            int slot = t + s * 256;
            int ls = slot & 31, tm = (slot >> 5) & 3, p = slot >> 7;
            sA[buf][tm][ls][p] = raA[s];
        }
        #pragma unroll
        for (int s = 0; s < 8; s++) {
            int slot = t + s * 256;
            int ls = slot & 31, tn = (slot >> 5) & 31, p = slot >> 10;
            sB[buf][tn][ls][p] = raB[s];
        }
    };
    auto compute = [&](int buf) {
        unsigned af[2][4], bf[8][2];
        #pragma unroll
        for (int i = 0; i < 2; i++)
            *(uint4*)af[i] = *(const uint4*)&sA[buf][wm * 2 + i][lane][0];
        #pragma unroll
        for (int j = 0; j < 8; j++)
            *(uint2*)bf[j] = *(const uint2*)&sB[buf][wn * 8 + j][lane][0];
        #pragma unroll
        for (int i = 0; i < 2; i++)
            #pragma unroll
            for (int j = 0; j < 8; j++)
                mma_bf16(acc[i][j], af[i], bf[j]);
    };

    const int S = LPAD / 16;   // 128 stages
    loadA(0); loadB(0); storeS(0);
    __syncthreads();
    for (int s = 0; s < S; s++) {
        if (s + 1 < S) { loadA((s + 1) * 16); loadB((s + 1) * 16); }
        compute(s & 1);
        if (s + 1 < S) storeS((s + 1) & 1);
        __syncthreads();
    }

    // rowsum lives at col 200: wn==3, j==1, (lane&3)==0, element 0 of each half
    if (wn == 3 && (lane & 3) == 0) {
        #pragma unroll
        for (int i = 0; i < 2; i++)
            #pragma unroll
            for (int h = 0; h < 2; h++)
                rowred[wm * 32 + i * 16 + (lane >> 2) + h * 8] = acc[i][1][h * 2];
    }
    __syncthreads();

    #pragma unroll
    for (int i = 0; i < 2; i++)
        #pragma unroll
        for (int h = 0; h < 2; h++) {
            int rloc = wm * 32 + i * 16 + (lane >> 2) + h * 8;
            int grow = m0 + rloc;
            if (grow < NLB) {
                float inv = 1.f / rowred[rloc];
                #pragma unroll
                for (int j = 0; j < 8; j++) {
                    int f = wn * 64 + j * 8 + (lane & 3) * 2;
                    if (f < FF) {
                        float2 o = make_float2(acc[i][j][h * 2 + 0] * inv,
                                               acc[i][j][h * 2 + 1] * inv);
                        *(float2*)&g_ao[((size_t)(b * NLB + grow)) * FF + f] = o;
                    }
                }
            }
        }
}

// ---------------- 5d. proj GEMM (tf32) fused with gemb dot -> logits ----------
__global__ void __launch_bounds__(256) k_projg(const float* __restrict__ Wo,
                                               const float* __restrict__ bo,
                                               float* __restrict__ out) {
    __shared__ __align__(16) unsigned sA[2][2][8][32][4];
    __shared__ __align__(16) unsigned sB[2][2][16][32][2];
    __shared__ float sred[256];

    int b  = blockIdx.y;
    int m0 = blockIdx.x * 128;
    const float* Ap = g_ao + (size_t)b * NLB * FF;

    int t = threadIdx.x, lane = t & 31, wid = t >> 5;
    int wm = wid >> 1, wn = wid & 1;

    float part[2][2] = {{0.f, 0.f}, {0.f, 0.f}};   // [i][row / row+8]
    float ra[2][4];
    float rb[4][2];
    float acc[2][8][4];

    auto loadA = [&](int k0) {
        #pragma unroll
        for (int s = 0; s < 2; s++) {
            int slot = t + s * 256;
            int ls = slot & 31, tm = (slot >> 5) & 7, k8 = slot >> 8;
            int r = m0 + tm * 16 + (ls >> 2);
            int c = k0 + k8 * 8 + (ls & 3);
            bool rv0 = r < NLB, rv1 = (r + 8) < NLB;
            bool cv0 = c < FF, cv1 = (c + 4) < FF;
            ra[s][0] = (rv0 && cv0) ? Ap[(size_t)r * FF + c]           : 0.f;
            ra[s][1] = (rv1 && cv0) ? Ap[(size_t)(r + 8) * FF + c]     : 0.f;
            ra[s][2] = (rv0 && cv1) ? Ap[(size_t)r * FF + c + 4]       : 0.f;
            ra[s][3] = (rv1 && cv1) ? Ap[(size_t)(r + 8) * FF + c + 4] : 0.f;
        }
    };
    auto loadB = [&](int k0, int n0) {
        #pragma unroll
        for (int s = 0; s < 4; s++) {
            int slot = t + s * 256;
            int ls = slot & 31, tn = (slot >> 5) & 15, k8 = slot >> 9;
            int k = k0 + k8 * 8 + (ls & 3);
            int n = n0 + tn * 8 + (ls >> 2);
            bool nv = n < FEAT;
            rb[s][0] = (k < FF && nv)       ? Wo[(size_t)k * FEAT + n]       : 0.f;
            rb[s][1] = ((k + 4) < FF && nv) ? Wo[(size_t)(k + 4) * FEAT + n] : 0.f;
        }
    };
    auto storeS = [&](int buf) {
        #pragma unroll
        for (int s = 0; s < 2; s++) {
            int slot = t + s * 256;
            int ls = slot & 31, tm = (slot >> 5) & 7, k8 = slot >> 8;
            unsigned* d = &sA[buf][k8][tm][ls][0];
            d[0] = cvt_tf32(ra[s][0]); d[1] = cvt_tf32(ra[s][1]);
            d[2] = cvt_tf32(ra[s][2]); d[3] = cvt_tf32(ra[s][3]);
        }
        #pragma unroll
        for (int s = 0; s < 4; s++) {
            int slot = t + s * 256;
            int ls = slot & 31, tn = (slot >> 5) & 15, k8 = slot >> 9;
            unsigned* d = &sB[buf][k8][tn][ls][0];
            d[0] = cvt_tf32(rb[s][0]); d[1] = cvt_tf32(rb[s][1]);
        }
    };
    auto compute = [&](int buf) {
        #pragma unroll
        for (int k8 = 0; k8 < 2; k8++) {
            unsigned af[2][4], bf[8][2];
            #pragma unroll
            for (int i = 0; i < 2; i++)
                *(uint4*)af[i] = *(const uint4*)&sA[buf][k8][wm * 2 + i][lane][0];
            #pragma unroll
            for (int j = 0; j < 8; j++)
                *(uint2*)bf[j] = *(const uint2*)&sB[buf][k8][wn * 8 + j][lane][0];
            #pragma unroll
            for (int i = 0; i < 2; i++)
                #pragma unroll
                for (int j = 0; j < 8; j++)
                    mma_tf32(acc[i][j], af[i], bf[j]);
        }
    };

    const int S = (FF + 15) / 16;    // 13
    for (int nt = 0; nt < 4; nt++) {
        int n0 = nt * 128;
        #pragma unroll
        for (int i = 0; i < 2; i++)
            #pragma unroll
            for (int j = 0; j < 8; j++)
                #pragma unroll
                for (int q = 0; q < 4; q++) acc[i][j][q] = 0.f;

        loadA(0); loadB(0, n0); storeS(0);
        __syncthreads();
        for (int s = 0; s < S; s++) {
            if (s + 1 < S) { loadA((s + 1) * 16); loadB((s + 1) * 16, n0); }
            compute(s & 1);
            if (s + 1 < S) storeS((s + 1) & 1);
            __syncthreads();
        }

        // fold: relu(acc + bo) * gemb into per-row partials
        #pragma unroll
        for (int i = 0; i < 2; i++) {
            int row = m0 + (wm * 2 + i) * 16 + (lane >> 2);
            const float* g0 = (row < NLB)     ? g_gemb + (size_t)row * FEAT       : g_gemb;
            const float* g1 = (row + 8 < NLB) ? g_gemb + (size_t)(row + 8) * FEAT : g_gemb;
            bool rv0 = row < NLB, rv1 = (row + 8) < NLB;
            #pragma unroll
            for (int j = 0; j < 8; j++) {
                int col = n0 + (wn * 8 + j) * 8 + (lane & 3) * 2;
                if (col < FEAT) {
                    float b0 = bo[col], b1 = bo[col + 1];
                    if (rv0)
                        part[i][0] += fmaxf(acc[i][j][0] + b0, 0.f) * g0[col]
                                    + fmaxf(acc[i][j][1] + b1, 0.f) * g0[col + 1];
                    if (rv1)
                        part[i][1] += fmaxf(acc[i][j][2] + b0, 0.f) * g1[col]
                                    + fmaxf(acc[i][j][3] + b1, 0.f) * g1[col + 1];
                }
            }
        }
        __syncthreads();
    }

    // reduce across quad lanes (cols), then across the 2 wn warps via smem
    #pragma unroll
    for (int i = 0; i < 2; i++) {
        #pragma unroll
        for (int h = 0; h < 2; h++) {
            float v = part[i][h];
            v += __shfl_xor_sync(~0u, v, 1);
            v += __shfl_xor_sync(~0u, v, 2);
            if ((lane & 3) == 0) {
                int rl = wm * 32 + i * 16 + (lane >> 2) + h * 8;
                sred[rl * 2 + wn] = v;
            }
        }
    }
    __syncthreads();
    if (t < 128) {
        int gn = m0 + t;
        if (gn < NLB)
            out[b * NLB + gn] = sred[t * 2] + sred[t * 2 + 1];
    }
}

// ---------------- 6. BCE loss (deterministic two-stage) -----------------------
__global__ void k_loss_part(const float* __restrict__ y, const float* __restrict__ logits) {
    __shared__ float red[256];
    float s = 0.f;
    for (int i = blockIdx.x * 256 + threadIdx.x; i < BB * NLB; i += 64 * 256) {
        float z = logits[i];
        float yy = y[i];
        s += fmaxf(z, 0.f) - z * yy + log1pf(expf(-fabsf(z)));
    }
    red[threadIdx.x] = s;
    __syncthreads();
    for (int o = 128; o; o >>= 1) {
        if (threadIdx.x < o) red[threadIdx.x] += red[threadIdx.x + o];
        __syncthreads();
    }
    if (threadIdx.x == 0) g_losspart[blockIdx.x] = red[0];
}

__global__ void k_loss_final(float* __restrict__ out) {
    if (threadIdx.x == 0) {
        float s = 0.f;
        for (int i = 0; i < 64; i++) s += g_losspart[i];
        out[BB * NLB] = s / (float)BB;
    }
}

// ---------------- launch -------------------------------------------------------
extern "C" void kernel_launch(void* const* d_in, const int* in_sizes, int n_in,
                              void* d_out, int out_size) {
    const int*   x     = (const int*)d_in[0];
    const float* y     = (const float*)d_in[1];
    const float* mask  = (const float*)d_in[2];
    const float* we    = (const float*)d_in[3];
    const int*   lidx  = (const int*)d_in[4];
    const float* lmask = (const float*)d_in[5];
    const float* adj   = (const float*)d_in[6];
    const float* nn    = (const float*)d_in[7];
    const float* Wg    = (const float*)d_in[8];
    const float* bg    = (const float*)d_in[9];
    const float* Wc    = (const float*)d_in[10];
    const float* bc    = (const float*)d_in[11];
    const float* Wp    = (const float*)d_in[12];
    const float* bp    = (const float*)d_in[13];
    const float* Wo    = (const float*)d_in[14];
    const float* bo    = (const float*)d_in[15];
    float* out = (float*)d_out;

    k_avg<<<NLB, 320>>>(we, lidx, lmask);
    k_graph<<<NLB, 320>>>(adj, nn, Wg, bg);

    dim3 ge((LL + 127) / 128, BB);
    k_embT<<<ge, 256>>>(x, mask, we);
    k_wct<<<(CKK * FF + 255) / 256, 256>>>(Wc);

    dim3 gv((LP + 127) / 128, 2, BB);        // 16 x 2 x 8
    k_convg<<<gv, 256>>>(bc);

    k_cprep<<<(BB * (LPAD / 2) * 256) / 256, 256>>>();

    dim3 gj((LP + 127) / 128, 3, BB);        // 16 x 3 x 8
    k_pjg<<<gj, 256>>>(Wp, bp);

    dim3 gs((NLB + 127) / 128, LPAD / 128, BB);      // 70 x 16 x 8
    k_scores<<<gs, 256>>>();

    dim3 go(BB, (NLB + 63) / 64);            // 8 x 140
    k_attnout<<<go, 256>>>();

    dim3 gp((NLB + 127) / 128, BB);          // 70 x 8
    k_projg<<<gp, 256>>>(Wo, bo, out);

    k_loss_part<<<64, 256>>>(y, out);
    k_loss_final<<<1, 32>>>(out);
}